// round 7
// baseline (speedup 1.0000x reference)
#include <cuda_runtime.h>

// ---------------------------------------------------------------------------
// DECOLA Stage2 assigner — fully fused: ONE kernel, one block per batch.
// Batches are independent (vmap axis). Per block: stage batch in smem,
// build exact CSR label buckets, rows pass (gmax + stable top-4), cols pass
// (first-index argmax + lq + counts), write outputs. Zero global scratch.
//
// Inputs (metadata order):
//   0: pred_logits_match (B,N,1) f32   -- unused
//   1: pred_boxes        (B,N,4) f32   -- unused
//   2: init_reference    (B,N,4) f32   -- proposals (cxcywh)
//   3: prompt_inds       (B,N)   i32
//   4: gt_labels         (B,M)   i32
//   5: gt_boxes          (B,M,4) f32
//   6: max_k             scalar  i32   (k derived from out_size)
// Output: concat(rows, cols, valid, sel_iou) each (B,M,k), float32.
// ---------------------------------------------------------------------------

#define BB      16            // batch (fixed for this problem)
#define NL      128           // label slots (L=80, padded to pow2)
#define NMAX    3072          // proposals per batch cap (N=3000)
#define MMAX    384           // GTs per batch cap (M=300)
#define TOPK    4
#define THREADS 1024
#define NP      3             // ceil(NMAX/THREADS)
#define NGROUP  (THREADS / 8) // 8-lane groups for rows pass
#define IMAXI   0x7fffffff

struct Smem {
    float4 pbox[NMAX];        // proposal xyxy
    float  pa  [NMAX];        // proposal area
    int    pidx[NMAX];        // CSR: proposal indices grouped by label
    float4 gbox[MMAX];
    float  ga  [MMAX];
    int    gl  [MMAX];        // gt labels
    int    gidx[MMAX];        // CSR: gt indices grouped by label
    float  gmax[MMAX];
    float  topv[MMAX * TOPK];
    int    topi[MMAX * TOPK];
    int    cnt [MMAX];
    int    pcnt[NL + 1];      // proposal CSR offsets (after prefix sum)
    int    gcnt[NL + 1];      // gt CSR offsets
    int    poff[NL];          // running scatter cursors
    int    goff[NL];
};

// IoU from explicit _rn intrinsics so the rows pass and cols pass produce
// BITWISE-identical values (lq needs v == gmax). Same function, same smem
// input bits, no FMA contraction possible inside the intrinsics.
__device__ __forceinline__ float iou_fn(float4 g, float ga, float4 p, float pa) {
    float x0 = fmaxf(g.x, p.x);
    float y0 = fmaxf(g.y, p.y);
    float x1 = fminf(g.z, p.z);
    float y1 = fminf(g.w, p.w);
    float w  = fmaxf(__fsub_rn(x1, x0), 0.0f);
    float h  = fmaxf(__fsub_rn(y1, y0), 0.0f);
    float it = __fmul_rn(w, h);
    float un = __fsub_rn(__fadd_rn(ga, pa), it);
    return __fdiv_rn(it, fmaxf(un, 1e-9f));
}

// Insert (v,i) into 4-entry list sorted by (value desc, index asc).
// Strict total order (indices distinct) -> insert-order independent;
// matches jax.lax.top_k stability (lower index first among equals).
__device__ __forceinline__ void ins4(float v, int i, float tv[TOPK], int ti[TOPK]) {
    if (v > tv[3] || (v == tv[3] && i < ti[3])) {
        if (v > tv[2] || (v == tv[2] && i < ti[2])) {
            tv[3] = tv[2]; ti[3] = ti[2];
            if (v > tv[1] || (v == tv[1] && i < ti[1])) {
                tv[2] = tv[1]; ti[2] = ti[1];
                if (v > tv[0] || (v == tv[0] && i < ti[0])) {
                    tv[1] = tv[0]; ti[1] = ti[0];
                    tv[0] = v;     ti[0] = i;
                } else { tv[1] = v; ti[1] = i; }
            } else { tv[2] = v; ti[2] = i; }
        } else { tv[3] = v; ti[3] = i; }
    }
}

__device__ __forceinline__ float4 cxcywh_to_xyxy(float4 c) {
    float4 x;
    x.x = c.x - 0.5f * c.z; x.y = c.y - 0.5f * c.w;
    x.z = c.x + 0.5f * c.z; x.w = c.y + 0.5f * c.w;
    return x;
}

__global__ __launch_bounds__(THREADS, 1)
void k_fused(const float4* __restrict__ props,
             const float4* __restrict__ gts,
             const int*    __restrict__ pinds,
             const int*    __restrict__ glabels,
             float*        __restrict__ out,
             int N, int M, int B, int K) {
    extern __shared__ char smem_raw[];
    Smem& s = *reinterpret_cast<Smem*>(smem_raw);

    const int b   = blockIdx.x;
    const int tid = threadIdx.x;

    // ---- zero label counters ----
    if (tid <= NL) { s.pcnt[tid] = 0; s.gcnt[tid] = 0; }
    __syncthreads();

    // ---- Phase A: load, convert, count labels ----
    int pl[NP];
#pragma unroll
    for (int i = 0; i < NP; i++) {
        int n = tid + i * THREADS;
        pl[i] = 0;
        if (n < N) {
            float4 x = cxcywh_to_xyxy(props[b * N + n]);
            float  a = __fmul_rn(__fsub_rn(x.z, x.x), __fsub_rn(x.w, x.y));
            s.pbox[n] = x;
            s.pa [n]  = a;
            int l = pinds[b * N + n];
            pl[i] = l;
            atomicAdd(&s.pcnt[l + 1], 1);
        }
    }
    for (int m = tid; m < M; m += THREADS) {
        float4 x = cxcywh_to_xyxy(gts[b * M + m]);
        float  a = __fmul_rn(__fsub_rn(x.z, x.x), __fsub_rn(x.w, x.y));
        s.gbox[m] = x;
        s.ga [m]  = a;
        int l = glabels[b * M + m];
        s.gl [m]  = l;
        atomicAdd(&s.gcnt[l + 1], 1);
    }
    __syncthreads();

    // ---- Phase B: Hillis-Steele prefix sum over NL labels (both arrays) ----
#pragma unroll
    for (int d = 1; d < NL; d <<= 1) {
        int pv = 0, gv = 0;
        if (tid < NL) {
            pv = s.pcnt[tid + 1];
            gv = s.gcnt[tid + 1];
            if (tid + 1 > d) {
                pv += s.pcnt[tid + 1 - d];
                gv += s.gcnt[tid + 1 - d];
            }
        }
        __syncthreads();
        if (tid < NL) { s.pcnt[tid + 1] = pv; s.gcnt[tid + 1] = gv; }
        __syncthreads();
    }
    if (tid < NL) { s.poff[tid] = s.pcnt[tid]; s.goff[tid] = s.gcnt[tid]; }
    __syncthreads();

    // ---- Phase C: CSR scatter (smem atomics; order-independent downstream) ----
#pragma unroll
    for (int i = 0; i < NP; i++) {
        int n = tid + i * THREADS;
        if (n < N) {
            int pos = atomicAdd(&s.poff[pl[i]], 1);
            s.pidx[pos] = n;
        }
    }
    for (int m = tid; m < M; m += THREADS) {
        int pos = atomicAdd(&s.goff[s.gl[m]], 1);
        s.gidx[pos] = m;
    }
    __syncthreads();

    // ---- Phase D: rows pass — 8 lanes per GT: gmax + stable top-4 ----
    {
        int group = tid >> 3;
        int sub   = tid & 7;
        // uniform trip count across the block -> full-mask shuffles are safe
        for (int m0 = 0; m0 < M; m0 += NGROUP) {
            int  m   = m0 + group;
            bool act = m < M;
            float tv[TOPK] = {-1.f, -1.f, -1.f, -1.f};
            int   ti[TOPK] = {IMAXI, IMAXI, IMAXI, IMAXI};
            float4 g = make_float4(0.f, 0.f, 0.f, 0.f);
            float  ga_ = 0.f;
            int o0 = 0, o1 = 0;
            if (act) {
                g   = s.gbox[m];
                ga_ = s.ga[m];
                int l = s.gl[m];
                o0 = s.pcnt[l];
                o1 = s.pcnt[l + 1];
            }
            for (int e = o0 + sub; e < o1; e += 8) {
                int n = s.pidx[e];
                float v = iou_fn(g, ga_, s.pbox[n], s.pa[n]);
                ins4(v, n, tv, ti);
            }
            // 3-step butterfly within each aligned 8-lane group
#pragma unroll
            for (int off = 4; off > 0; off >>= 1) {
                float ov[TOPK]; int oi[TOPK];
#pragma unroll
                for (int j = 0; j < TOPK; j++) {
                    ov[j] = __shfl_xor_sync(0xffffffffu, tv[j], off);
                    oi[j] = __shfl_xor_sync(0xffffffffu, ti[j], off);
                }
#pragma unroll
                for (int j = 0; j < TOPK; j++) ins4(ov[j], oi[j], tv, ti);
            }
            if (act && sub == 0) {
                s.gmax[m] = tv[0];        // -1 when row has no match (== ref NEG)
#pragma unroll
                for (int j = 0; j < TOPK; j++) {
                    s.topv[m * TOPK + j] = tv[j];
                    s.topi[m * TOPK + j] = ti[j];
                }
                s.cnt[m] = 0;
            }
        }
    }
    __syncthreads();

    // ---- Phase E: cols pass — per-proposal argmax / lq / counts ----
#pragma unroll
    for (int i = 0; i < NP; i++) {
        int n = tid + i * THREADS;
        if (n < N) {
            int    l   = pl[i];
            float4 p   = s.pbox[n];
            float  pa_ = s.pa[n];
            int o0 = s.gcnt[l];
            int o1 = s.gcnt[l + 1];
            float best = -2.0f;
            int   bg   = IMAXI;
            bool  lq   = false;
            for (int e = o0; e < o1; e++) {
                int gi = s.gidx[e];
                float v = iou_fn(s.gbox[gi], s.ga[gi], p, pa_);
                // lexicographic (v desc, m asc) == JAX first-index argmax over
                // matched entries; unmatched rows (-1) never win when a match
                // exists, and pos=false when none exists.
                if (v > best || (v == best && gi < bg)) { best = v; bg = gi; }
                lq = lq || (v == s.gmax[gi]);   // bitwise vs rows pass
            }
            if (best >= 0.6f || lq) atomicAdd(&s.cnt[bg], 1);
        }
    }
    __syncthreads();

    // ---- Phase F: write rows | cols | valid | sel_iou ----
    {
        int S = B * M * K;
        for (int e = tid; e < M * K; e += THREADS) {
            int  m    = e / K;
            int  j    = e - m * K;
            bool val  = j < min(s.cnt[m], K);
            int  o    = b * M * K + e;
            out[        o] = val ? (float)s.topi[m * TOPK + j] : -1.0f;
            out[    S + o] = val ? (float)m                    : -1.0f;
            out[2 * S + o] = val ? 1.0f : 0.0f;
            out[3 * S + o] = val ? s.topv[m * TOPK + j]        : 0.0f;
        }
    }
}

// ---------------------------------------------------------------------------
extern "C" void kernel_launch(void* const* d_in, const int* in_sizes, int n_in,
                              void* d_out, int out_size) {
    const float4* props   = (const float4*)d_in[2];
    const int*    pinds   = (const int*)   d_in[3];
    const int*    glabels = (const int*)   d_in[4];
    const float4* gts     = (const float4*)d_in[5];

    const int B  = BB;
    int BN = in_sizes[3];
    int BM = in_sizes[4];
    int N  = BN / B;
    int M  = BM / B;
    int K  = out_size / (4 * BM);
    if (K > TOPK) K = TOPK;
    if (K < 1)    K = 1;

    // Opt in to >48KB dynamic smem (attribute set, not an allocation; host-side
    // call that is not a stream operation, so it is graph-capture safe).
    cudaFuncSetAttribute(k_fused, cudaFuncAttributeMaxDynamicSharedMemorySize,
                         (int)sizeof(Smem));

    k_fused<<<B, THREADS, sizeof(Smem)>>>(props, gts, pinds, glabels,
                                          (float*)d_out, N, M, B, K);
}